// round 2
// baseline (speedup 1.0000x reference)
#include <cuda_runtime.h>

#define MAP_W 64
#define MAP_H 64
#define T_SIZE 64
#define NUM_CP 8
#define BATCH 128

// Per-(b,t) packed parameters: [mx, my, u00, u01, u11, mconst, pad, pad]
// m(x,y) = u00*dx*dx + u01*dx*dy + u11*dy*dy + mconst   (log2 domain, scale folded in)
__device__ float g_params[BATCH * T_SIZE * 8];

__global__ void params_kernel(const float* __restrict__ cp_means,
                              const int* __restrict__ num_cps_raw,
                              const float* __restrict__ cp_cov) {
    int idx = blockIdx.x * blockDim.x + threadIdx.x;
    if (idx >= BATCH * T_SIZE) return;
    int b  = idx >> 6;
    int ti = idx & 63;
    float t = (float)ti * (1.0f / 63.0f);
    float u = 1.0f - t;

    // Runtime dtype detection for num_cps: values are in [3,8], so if the
    // buffer is int64 the second 32-bit word is the hi word == 0.
    bool is64 = (num_cps_raw[1] == 0);
    int ncps = is64 ? num_cps_raw[2 * b] : num_cps_raw[b];
    int n = ncps - 1;  // 2..7

    // power tables t^j, u^j
    float tp[NUM_CP], up[NUM_CP];
    tp[0] = 1.0f; up[0] = 1.0f;
#pragma unroll
    for (int j = 1; j < NUM_CP; j++) { tp[j] = tp[j - 1] * t; up[j] = up[j - 1] * u; }

    float coef = 1.0f;  // C(n,k), iterative
    float mx = 0.0f, my = 0.0f;
    float ca = 0.0f, cb = 0.0f, cd = 0.0f;
#pragma unroll
    for (int k = 0; k < NUM_CP; k++) {
        float wk = 0.0f;
        if (k <= n) {
            wk = coef * tp[k] * up[n - k];
            coef = coef * (float)(n - k) / (float)(k + 1);
        }
        int base = k * BATCH + b;
        mx += wk * cp_means[base * 2 + 0];
        my += wk * cp_means[base * 2 + 1];
        float w2 = wk * wk;
        ca += w2 * cp_cov[base * 4 + 0];
        cb += w2 * cp_cov[base * 4 + 1];
        cd += w2 * cp_cov[base * 4 + 3];
    }

    float det = ca * cd - cb * cb;
    float rdet = 1.0f / det;
    float inv00 = cd * rdet;
    float inv01 = -cb * rdet;
    float inv11 = ca * rdet;

    const float L = 1.44269504088896340736f;  // log2(e)
    // log2( 1/(2*pi*sqrt(det)) ) = -log2(2*pi) - 0.5*log2(det)
    float mconst = -2.651496129472319f - 0.5f * log2f(det);

    float* o = &g_params[idx * 8];
    o[0] = mx;
    o[1] = my;
    o[2] = -0.5f * L * inv00;
    o[3] = -L * inv01;          // cross term: -0.5 * 2 * inv01
    o[4] = -0.5f * L * inv11;
    o[5] = mconst;
    o[6] = 0.0f;
    o[7] = 0.0f;
}

__device__ __forceinline__ float ex2f(float x) {
    float y;
    asm("ex2.approx.ftz.f32 %0, %1;" : "=f"(y) : "f"(x));
    return y;
}

// Output layout: out[b][x][y][t], t contiguous.
// Block: 256 threads. lane tq = tid&15 owns t in [4*tq, 4*tq+4); sub = tid>>4
// picks the pixel. A warp writes 2 pixels x full 64-t row = 512B contiguous.
// Grid: 128 b * 16 pixel-groups = 2048 blocks; 16 unrolled iterations each.
__global__ __launch_bounds__(256) void map_kernel(float* __restrict__ out) {
    int blk = blockIdx.x;
    int b = blk >> 4;
    int pixBase = (blk & 15) * 256;
    int tid = threadIdx.x;
    int tq = tid & 15;
    int sub = tid >> 4;

    const float4* P = (const float4*)&g_params[(b * 64 + tq * 4) * 8];
    float4 a0 = P[0], b0 = P[1];
    float4 a1 = P[2], b1 = P[3];
    float4 a2 = P[4], b2 = P[5];
    float4 a3 = P[6], b3 = P[7];

    float* obase = out + ((size_t)(b * 4096 + pixBase + sub)) * 64 + tq * 4;

#pragma unroll
    for (int i = 0; i < 16; i++) {
        int pid = pixBase + i * 16 + sub;
        float xf = (float)(pid >> 6);
        float yf = (float)(pid & 63);
        float4 r;
        {
            float dx = xf - a0.x, dy = yf - a0.y;
            float m = fmaf(a0.z * dx, dx, b0.y);
            m = fmaf(a0.w * dx, dy, m);
            m = fmaf(b0.x * dy, dy, m);
            r.x = ex2f(m);
        }
        {
            float dx = xf - a1.x, dy = yf - a1.y;
            float m = fmaf(a1.z * dx, dx, b1.y);
            m = fmaf(a1.w * dx, dy, m);
            m = fmaf(b1.x * dy, dy, m);
            r.y = ex2f(m);
        }
        {
            float dx = xf - a2.x, dy = yf - a2.y;
            float m = fmaf(a2.z * dx, dx, b2.y);
            m = fmaf(a2.w * dx, dy, m);
            m = fmaf(b2.x * dy, dy, m);
            r.z = ex2f(m);
        }
        {
            float dx = xf - a3.x, dy = yf - a3.y;
            float m = fmaf(a3.z * dx, dx, b3.y);
            m = fmaf(a3.w * dx, dy, m);
            m = fmaf(b3.x * dy, dy, m);
            r.w = ex2f(m);
        }
        *(float4*)(obase + (size_t)i * 1024) = r;
    }
}

extern "C" void kernel_launch(void* const* d_in, const int* in_sizes, int n_in,
                              void* d_out, int out_size) {
    const float* cp_means = (const float*)d_in[0];
    const int*   num_cps  = (const int*)d_in[1];
    const float* cp_cov   = (const float*)d_in[2];
    float* out = (float*)d_out;

    params_kernel<<<64, 128>>>(cp_means, num_cps, cp_cov);
    map_kernel<<<2048, 256>>>(out);
}

// round 4
// speedup vs baseline: 1.0789x; 1.0789x over previous
#include <cuda_runtime.h>

#define MAP_W 64
#define MAP_H 64
#define T_SIZE 64
#define NUM_CP 8
#define BATCH 128

__device__ __forceinline__ float ex2f(float x) {
    float y;
    asm("ex2.approx.ftz.f32 %0, %1;" : "=f"(y) : "f"(x));
    return y;
}

// Fused kernel. Grid = 128 b * 16 pixel-groups = 2048 blocks, 256 threads.
// Phase 1: threads 0..63 compute per-(b,t) Gaussian params for all 64 t into
//          shared memory (SoA).
// Phase 2: lane tq = tid&15 owns t in [4*tq, 4*tq+4); sub = tid>>4 picks the
//          pixel within the group. Each STG.128 warp-op writes 512 B fully
//          contiguous.
__global__ __launch_bounds__(256) void fused_map_kernel(
    const float* __restrict__ cp_means,
    const int* __restrict__ num_cps_raw,
    const float* __restrict__ cp_cov,
    float* __restrict__ out) {
    __shared__ float s_mx[64], s_my[64], s_qa[64], s_qb[64], s_qc[64], s_mc[64];

    int blk = blockIdx.x;
    int b = blk >> 4;
    int pixBase = (blk & 15) * 256;
    int tid = threadIdx.x;

    if (tid < 64) {
        int ti = tid;
        float t = (float)ti * (1.0f / 63.0f);
        float u = 1.0f - t;

        // Runtime dtype detection for num_cps: values are in [3,8], so if the
        // buffer is int64 (little-endian) the second 32-bit word is hi == 0.
        bool is64 = (num_cps_raw[1] == 0);
        int ncps = is64 ? num_cps_raw[2 * b] : num_cps_raw[b];
        int n = ncps - 1;  // 2..7

        float tp[NUM_CP], up[NUM_CP];
        tp[0] = 1.0f; up[0] = 1.0f;
#pragma unroll
        for (int j = 1; j < NUM_CP; j++) { tp[j] = tp[j - 1] * t; up[j] = up[j - 1] * u; }

        float coef = 1.0f;  // C(n,k), iterative — exact for n<=7
        float mx = 0.0f, my = 0.0f;
        float ca = 0.0f, cb = 0.0f, cd = 0.0f;
#pragma unroll
        for (int k = 0; k < NUM_CP; k++) {
            float wk = 0.0f;
            if (k <= n) {
                wk = coef * tp[k] * up[n - k];
                coef = coef * (float)(n - k) / (float)(k + 1);
            }
            int base = k * BATCH + b;
            mx += wk * cp_means[base * 2 + 0];
            my += wk * cp_means[base * 2 + 1];
            float w2 = wk * wk;
            ca += w2 * cp_cov[base * 4 + 0];
            cb += w2 * cp_cov[base * 4 + 1];
            cd += w2 * cp_cov[base * 4 + 3];
        }

        float det = ca * cd - cb * cb;
        float rdet = 1.0f / det;
        const float L = 1.44269504088896340736f;  // log2(e)
        s_mx[ti] = mx;
        s_my[ti] = my;
        s_qa[ti] = -0.5f * L * cd * rdet;   // -0.5*L*inv00
        s_qb[ti] =  L * cb * rdet;          // -L*inv01   (inv01 = -cb*rdet)
        s_qc[ti] = -0.5f * L * ca * rdet;   // -0.5*L*inv11
        // log2( 1/(2*pi*sqrt(det)) ) = -log2(2*pi) - 0.5*log2(det)
        s_mc[ti] = -2.651496129472319f - 0.5f * log2f(det);
    }
    __syncthreads();

    int tq = tid & 15;
    int sub = tid >> 4;
    int t0 = tq * 4;

    // 24 param registers for this lane's 4 t-values
    float mx0 = s_mx[t0 + 0], my0 = s_my[t0 + 0], qa0 = s_qa[t0 + 0], qb0 = s_qb[t0 + 0], qc0 = s_qc[t0 + 0], mc0 = s_mc[t0 + 0];
    float mx1 = s_mx[t0 + 1], my1 = s_my[t0 + 1], qa1 = s_qa[t0 + 1], qb1 = s_qb[t0 + 1], qc1 = s_qc[t0 + 1], mc1 = s_mc[t0 + 1];
    float mx2 = s_mx[t0 + 2], my2 = s_my[t0 + 2], qa2 = s_qa[t0 + 2], qb2 = s_qb[t0 + 2], qc2 = s_qc[t0 + 2], mc2 = s_mc[t0 + 2];
    float mx3 = s_mx[t0 + 3], my3 = s_my[t0 + 3], qa3 = s_qa[t0 + 3], qb3 = s_qb[t0 + 3], qc3 = s_qc[t0 + 3], mc3 = s_mc[t0 + 3];

    float* obase = out + ((size_t)(b * 4096 + pixBase + sub)) * 64 + t0;

#pragma unroll
    for (int i = 0; i < 16; i++) {
        int pid = pixBase + i * 16 + sub;
        float xf = (float)(pid >> 6);
        float yf = (float)(pid & 63);
        float4 r;
        {
            float dx = xf - mx0, dy = yf - my0;
            float m = fmaf(qa0 * dx, dx, mc0);
            m = fmaf(qb0 * dx, dy, m);
            m = fmaf(qc0 * dy, dy, m);
            r.x = ex2f(m);
        }
        {
            float dx = xf - mx1, dy = yf - my1;
            float m = fmaf(qa1 * dx, dx, mc1);
            m = fmaf(qb1 * dx, dy, m);
            m = fmaf(qc1 * dy, dy, m);
            r.y = ex2f(m);
        }
        {
            float dx = xf - mx2, dy = yf - my2;
            float m = fmaf(qa2 * dx, dx, mc2);
            m = fmaf(qb2 * dx, dy, m);
            m = fmaf(qc2 * dy, dy, m);
            r.z = ex2f(m);
        }
        {
            float dx = xf - mx3, dy = yf - my3;
            float m = fmaf(qa3 * dx, dx, mc3);
            m = fmaf(qb3 * dx, dy, m);
            m = fmaf(qc3 * dy, dy, m);
            r.w = ex2f(m);
        }
        *(float4*)(obase + (size_t)i * 1024) = r;
    }
}

extern "C" void kernel_launch(void* const* d_in, const int* in_sizes, int n_in,
                              void* d_out, int out_size) {
    const float* cp_means = (const float*)d_in[0];
    const int*   num_cps  = (const int*)d_in[1];
    const float* cp_cov   = (const float*)d_in[2];
    float* out = (float*)d_out;

    fused_map_kernel<<<2048, 256>>>(cp_means, num_cps, cp_cov, out);
}

// round 5
// speedup vs baseline: 1.0846x; 1.0052x over previous
#include <cuda_runtime.h>

#define MAP_W 64
#define MAP_H 64
#define T_SIZE 64
#define NUM_CP 8
#define BATCH 128

__device__ __forceinline__ float ex2f(float x) {
    float y;
    asm("ex2.approx.ftz.f32 %0, %1;" : "=f"(y) : "f"(x));
    return y;
}

// Fused single-wave kernel. Grid = 128 b * 4 pixel-groups = 512 blocks,
// 256 threads — at most ~3.5 blocks/SM, everything resident in one wave.
// Phase 1: threads 0..63 compute per-(b,t) Gaussian params for all 64 t into
//          shared memory (SoA).
// Phase 2: lane tq = tid&15 owns t in [4*tq, 4*tq+4); sub = tid>>4 picks the
//          pixel. 64 iterations; each STG.128 warp-op writes 512 B contiguous.
__global__ __launch_bounds__(256) void fused_map_kernel(
    const float* __restrict__ cp_means,
    const int* __restrict__ num_cps_raw,
    const float* __restrict__ cp_cov,
    float* __restrict__ out) {
    __shared__ float s_mx[64], s_my[64], s_qa[64], s_qb[64], s_qc[64], s_mc[64];

    int blk = blockIdx.x;
    int b = blk >> 2;
    int pixBase = (blk & 3) * 1024;
    int tid = threadIdx.x;

    if (tid < 64) {
        int ti = tid;
        float t = (float)ti * (1.0f / 63.0f);
        float u = 1.0f - t;

        // Runtime dtype detection for num_cps: values are in [3,8], so if the
        // buffer is int64 (little-endian) the second 32-bit word is hi == 0.
        bool is64 = (num_cps_raw[1] == 0);
        int ncps = is64 ? num_cps_raw[2 * b] : num_cps_raw[b];
        int n = ncps - 1;  // 2..7

        float tp[NUM_CP], up[NUM_CP];
        tp[0] = 1.0f; up[0] = 1.0f;
#pragma unroll
        for (int j = 1; j < NUM_CP; j++) { tp[j] = tp[j - 1] * t; up[j] = up[j - 1] * u; }

        float coef = 1.0f;  // C(n,k), iterative — exact for n<=7
        float mx = 0.0f, my = 0.0f;
        float ca = 0.0f, cb = 0.0f, cd = 0.0f;
#pragma unroll
        for (int k = 0; k < NUM_CP; k++) {
            float wk = 0.0f;
            if (k <= n) {
                wk = coef * tp[k] * up[n - k];
                coef = coef * (float)(n - k) / (float)(k + 1);
            }
            int base = k * BATCH + b;
            mx += wk * cp_means[base * 2 + 0];
            my += wk * cp_means[base * 2 + 1];
            float w2 = wk * wk;
            ca += w2 * cp_cov[base * 4 + 0];
            cb += w2 * cp_cov[base * 4 + 1];
            cd += w2 * cp_cov[base * 4 + 3];
        }

        float det = ca * cd - cb * cb;
        float rdet = 1.0f / det;
        const float L = 1.44269504088896340736f;  // log2(e)
        s_mx[ti] = mx;
        s_my[ti] = my;
        s_qa[ti] = -0.5f * L * cd * rdet;   // -0.5*L*inv00
        s_qb[ti] =  L * cb * rdet;          // -L*inv01   (inv01 = -cb*rdet)
        s_qc[ti] = -0.5f * L * ca * rdet;   // -0.5*L*inv11
        // log2( 1/(2*pi*sqrt(det)) ) = -log2(2*pi) - 0.5*log2(det)
        s_mc[ti] = -2.651496129472319f - 0.5f * log2f(det);
    }
    __syncthreads();

    int tq = tid & 15;
    int sub = tid >> 4;
    int t0 = tq * 4;

    // 24 param registers for this lane's 4 t-values
    float mx0 = s_mx[t0 + 0], my0 = s_my[t0 + 0], qa0 = s_qa[t0 + 0], qb0 = s_qb[t0 + 0], qc0 = s_qc[t0 + 0], mc0 = s_mc[t0 + 0];
    float mx1 = s_mx[t0 + 1], my1 = s_my[t0 + 1], qa1 = s_qa[t0 + 1], qb1 = s_qb[t0 + 1], qc1 = s_qc[t0 + 1], mc1 = s_mc[t0 + 1];
    float mx2 = s_mx[t0 + 2], my2 = s_my[t0 + 2], qa2 = s_qa[t0 + 2], qb2 = s_qb[t0 + 2], qc2 = s_qc[t0 + 2], mc2 = s_mc[t0 + 2];
    float mx3 = s_mx[t0 + 3], my3 = s_my[t0 + 3], qa3 = s_qa[t0 + 3], qb3 = s_qb[t0 + 3], qc3 = s_qc[t0 + 3], mc3 = s_mc[t0 + 3];

    float* obase = out + ((size_t)(b * 4096 + pixBase + sub)) * 64 + t0;

#pragma unroll 4
    for (int o = 0; o < 4; o++) {
#pragma unroll
        for (int ii = 0; ii < 16; ii++) {
            int i = o * 16 + ii;
            int pid = pixBase + i * 16 + sub;
            float xf = (float)(pid >> 6);
            float yf = (float)(pid & 63);
            float4 r;
            {
                float dx = xf - mx0, dy = yf - my0;
                float m = fmaf(qa0 * dx, dx, mc0);
                m = fmaf(qb0 * dx, dy, m);
                m = fmaf(qc0 * dy, dy, m);
                r.x = ex2f(m);
            }
            {
                float dx = xf - mx1, dy = yf - my1;
                float m = fmaf(qa1 * dx, dx, mc1);
                m = fmaf(qb1 * dx, dy, m);
                m = fmaf(qc1 * dy, dy, m);
                r.y = ex2f(m);
            }
            {
                float dx = xf - mx2, dy = yf - my2;
                float m = fmaf(qa2 * dx, dx, mc2);
                m = fmaf(qb2 * dx, dy, m);
                m = fmaf(qc2 * dy, dy, m);
                r.z = ex2f(m);
            }
            {
                float dx = xf - mx3, dy = yf - my3;
                float m = fmaf(qa3 * dx, dx, mc3);
                m = fmaf(qb3 * dx, dy, m);
                m = fmaf(qc3 * dy, dy, m);
                r.w = ex2f(m);
            }
            *(float4*)(obase + (size_t)i * 1024) = r;
        }
    }
}

extern "C" void kernel_launch(void* const* d_in, const int* in_sizes, int n_in,
                              void* d_out, int out_size) {
    const float* cp_means = (const float*)d_in[0];
    const int*   num_cps  = (const int*)d_in[1];
    const float* cp_cov   = (const float*)d_in[2];
    float* out = (float*)d_out;

    fused_map_kernel<<<512, 256>>>(cp_means, num_cps, cp_cov, out);
}

// round 6
// speedup vs baseline: 1.0971x; 1.0116x over previous
#include <cuda_runtime.h>

#define MAP_W 64
#define MAP_H 64
#define T_SIZE 64
#define NUM_CP 8
#define BATCH 128

__device__ __forceinline__ float ex2f(float x) {
    float y;
    asm("ex2.approx.ftz.f32 %0, %1;" : "=f"(y) : "f"(x));
    return y;
}

union f2u { float2 f; unsigned long long u; };

__device__ __forceinline__ float2 ffma2(float2 a, float2 b, float2 c) {
    f2u A, B, C, D; A.f = a; B.f = b; C.f = c;
    asm("fma.rn.f32x2 %0, %1, %2, %3;" : "=l"(D.u) : "l"(A.u), "l"(B.u), "l"(C.u));
    return D.f;
}

__device__ __forceinline__ float2 fadd2(float2 a, float2 b) {
    f2u A, B, D; A.f = a; B.f = b;
    asm("add.rn.f32x2 %0, %1, %2;" : "=l"(D.u) : "l"(A.u), "l"(B.u));
    return D.f;
}

// Fused kernel, Horner-in-y + packed f32x2 math.
// Grid = 128 b * 4 pixel-groups = 512 blocks, 256 threads.
// Phase 1: threads 0..63 compute per-(b,t) Gaussian params into smem (SoA).
// Phase 2: lane tq=tid&15 owns t in [4tq,4tq+4) as two f32x2 pairs; sub=tid>>4
//          picks the pixel. m(y) = qc*y^2 + C1(x)*y + C0(x); C1/C0 hoisted per
//          x-phase (4 iters). Each STG.128 warp-op writes 512 B contiguous.
__global__ __launch_bounds__(256) void fused_map_kernel(
    const float* __restrict__ cp_means,
    const int* __restrict__ num_cps_raw,
    const float* __restrict__ cp_cov,
    float* __restrict__ out) {
    __shared__ float s_mx[64], s_my[64], s_qa[64], s_qb[64], s_qc[64], s_mc[64];

    int blk = blockIdx.x;
    int b = blk >> 2;
    int pixBase = (blk & 3) * 1024;
    int tid = threadIdx.x;

    if (tid < 64) {
        int ti = tid;
        float t = (float)ti * (1.0f / 63.0f);
        float u = 1.0f - t;

        // Runtime dtype detection for num_cps: values in [3,8], so if the
        // buffer is int64 (little-endian) the second 32-bit word is hi == 0.
        bool is64 = (num_cps_raw[1] == 0);
        int ncps = is64 ? num_cps_raw[2 * b] : num_cps_raw[b];
        int n = ncps - 1;  // 2..7

        float tp[NUM_CP], up[NUM_CP];
        tp[0] = 1.0f; up[0] = 1.0f;
#pragma unroll
        for (int j = 1; j < NUM_CP; j++) { tp[j] = tp[j - 1] * t; up[j] = up[j - 1] * u; }

        float coef = 1.0f;  // C(n,k), iterative — exact for n<=7
        float mx = 0.0f, my = 0.0f;
        float ca = 0.0f, cb = 0.0f, cd = 0.0f;
#pragma unroll
        for (int k = 0; k < NUM_CP; k++) {
            float wk = 0.0f;
            if (k <= n) {
                wk = coef * tp[k] * up[n - k];
                coef = coef * (float)(n - k) / (float)(k + 1);
            }
            int base = k * BATCH + b;
            mx += wk * cp_means[base * 2 + 0];
            my += wk * cp_means[base * 2 + 1];
            float w2 = wk * wk;
            ca += w2 * cp_cov[base * 4 + 0];
            cb += w2 * cp_cov[base * 4 + 1];
            cd += w2 * cp_cov[base * 4 + 3];
        }

        float det = ca * cd - cb * cb;
        float rdet = 1.0f / det;
        const float L = 1.44269504088896340736f;  // log2(e)
        s_mx[ti] = mx;
        s_my[ti] = my;
        s_qa[ti] = -0.5f * L * cd * rdet;   // -0.5*L*inv00
        s_qb[ti] =  L * cb * rdet;          // -L*inv01   (inv01 = -cb*rdet)
        s_qc[ti] = -0.5f * L * ca * rdet;   // -0.5*L*inv11
        // log2( 1/(2*pi*sqrt(det)) ) = -log2(2*pi) - 0.5*log2(det)
        s_mc[ti] = -2.651496129472319f - 0.5f * log2f(det);
    }
    __syncthreads();

    int tq = tid & 15;
    int sub = tid >> 4;
    int t0 = tq * 4;

    // Packed per-pair constants for t-pairs (t0,t0+1) and (t0+2,t0+3):
    //   m(x,y) = qc*y^2 + (qb*dx + c1b)*y + ((qa*dx + c0b)*dx + c0c)
    //   c1b = -2*qc*my ;  c0b = -qb*my ;  c0c = qc*my^2 + mc ;  dx = x - mx
    float2 qaP[2], qbP[2], qcP[2], nmxP[2], c1bP[2], c0bP[2], c0cP[2];
#pragma unroll
    for (int p = 0; p < 2; p++) {
        int ta = t0 + 2 * p;
        float qa0 = s_qa[ta],     qa1 = s_qa[ta + 1];
        float qb0 = s_qb[ta],     qb1 = s_qb[ta + 1];
        float qc0 = s_qc[ta],     qc1 = s_qc[ta + 1];
        float mx0 = s_mx[ta],     mx1 = s_mx[ta + 1];
        float my0 = s_my[ta],     my1 = s_my[ta + 1];
        float mc0 = s_mc[ta],     mc1 = s_mc[ta + 1];
        qaP[p]  = make_float2(qa0, qa1);
        qbP[p]  = make_float2(qb0, qb1);
        qcP[p]  = make_float2(qc0, qc1);
        nmxP[p] = make_float2(-mx0, -mx1);
        c1bP[p] = make_float2(-2.0f * qc0 * my0, -2.0f * qc1 * my1);
        c0bP[p] = make_float2(-qb0 * my0, -qb1 * my1);
        c0cP[p] = make_float2(fmaf(qc0 * my0, my0, mc0), fmaf(qc1 * my1, my1, mc1));
    }

    // 4 distinct y values per block: y = 16*j + sub, j = 0..3 (packed, reused)
    float subf = (float)sub;
    float2 yyP[4];
#pragma unroll
    for (int j = 0; j < 4; j++) {
        float yv = subf + 16.0f * (float)j;
        yyP[j] = make_float2(yv, yv);
    }

    float basex = (float)(pixBase >> 6);
    float* obase = out + ((size_t)(b * 4096 + pixBase + sub)) * 64 + t0;

#pragma unroll
    for (int xi = 0; xi < 16; xi++) {
        float xf = basex + (float)xi;
        float2 xx = make_float2(xf, xf);
        float2 C1[2], C0[2];
#pragma unroll
        for (int p = 0; p < 2; p++) {
            float2 dx = fadd2(xx, nmxP[p]);
            C1[p] = ffma2(qbP[p], dx, c1bP[p]);
            C0[p] = ffma2(ffma2(qaP[p], dx, c0bP[p]), dx, c0cP[p]);
        }
#pragma unroll
        for (int j = 0; j < 4; j++) {
            float2 m0 = ffma2(ffma2(qcP[0], yyP[j], C1[0]), yyP[j], C0[0]);
            float2 m1 = ffma2(ffma2(qcP[1], yyP[j], C1[1]), yyP[j], C0[1]);
            float4 r;
            r.x = ex2f(m0.x);
            r.y = ex2f(m0.y);
            r.z = ex2f(m1.x);
            r.w = ex2f(m1.y);
            *(float4*)(obase + (size_t)(xi * 4 + j) * 1024) = r;
        }
    }
}

extern "C" void kernel_launch(void* const* d_in, const int* in_sizes, int n_in,
                              void* d_out, int out_size) {
    const float* cp_means = (const float*)d_in[0];
    const int*   num_cps  = (const int*)d_in[1];
    const float* cp_cov   = (const float*)d_in[2];
    float* out = (float*)d_out;

    fused_map_kernel<<<512, 256>>>(cp_means, num_cps, cp_cov, out);
}